// round 14
// baseline (speedup 1.0000x reference)
#include <cuda_runtime.h>
#include <cuda_fp8.h>
#include <cstdint>
#include <math.h>

#define NROWS 4096
#define DIM   1024
#define MARGIN 0.5f
#define EPSN   1e-8f

#define BM 128
#define BN 64
#define BK 64                 // 64 fp8 bytes per k-chunk
#define KT (DIM / BK)         // 16
#define STAGES 4
#define SROW 80               // padded smem row stride (bytes) for 64B of data
#define STAGE_A (BM * SROW)                    // 10240
#define STAGE_B (BN * SROW)                    // 5120
#define STAGE_BYTES (STAGE_A + STAGE_B)        // 15360
#define SMEM_BYTES (STAGES * STAGE_BYTES)      // 61440

#define NBLK_I (NROWS / BM)   // 32
#define NBLK_J (NROWS / BN)   // 64
#define NBLKS  (NBLK_I * NBLK_J)

// Scratch (device globals; rewritten every call)
__device__ uint8_t g_img_f8[NROWS * DIM];
__device__ uint8_t g_txt_f8[NROWS * DIM];
__device__ float g_rnorm_img[NROWS];
__device__ float g_rnorm_txt[NROWS];
__device__ float g_pos_part[NROWS];
__device__ float g_neg_part[NBLKS];

__device__ __forceinline__ uint32_t smem_u32(const void* p) {
    uint32_t a;
    asm("{ .reg .u64 t; cvta.to.shared.u64 t, %1; cvt.u32.u64 %0, t; }" : "=r"(a) : "l"(p));
    return a;
}

__device__ __forceinline__ float warp_sum(float v) {
    #pragma unroll
    for (int o = 16; o > 0; o >>= 1) v += __shfl_down_sync(0xffffffffu, v, o);
    return v;
}

__device__ __forceinline__ uint32_t pack4_e4m3(float4 v) {
    __nv_fp8x2_storage_t lo = __nv_cvt_float2_to_fp8x2(make_float2(v.x, v.y),
                                                       __NV_SATFINITE, __NV_E4M3);
    __nv_fp8x2_storage_t hi = __nv_cvt_float2_to_fp8x2(make_float2(v.z, v.w),
                                                       __NV_SATFINITE, __NV_E4M3);
    return (uint32_t)lo | ((uint32_t)hi << 16);
}

// Fused: fp32 read -> fp8 copies + norms + positive-loss partial. 4 rows per block.
// R11 layout: per-instruction coalesced loads (stride 64 float4 across j), MLP=8.
__global__ void __launch_bounds__(256) row_stats_convert_kernel(
    const float* __restrict__ img, const float* __restrict__ txt)
{
    const int t   = threadIdx.x;
    const int rl  = t >> 6;
    const int c   = t & 63;
    const int row = blockIdx.x * 4 + rl;

    const float4* ip = reinterpret_cast<const float4*>(img + (size_t)row * DIM);
    const float4* tp = reinterpret_cast<const float4*>(txt + (size_t)row * DIM);
    uint32_t* ib = reinterpret_cast<uint32_t*>(g_img_f8 + (size_t)row * DIM);
    uint32_t* tb = reinterpret_cast<uint32_t*>(g_txt_f8 + (size_t)row * DIM);

    float4 ra[4], rb[4];
    #pragma unroll
    for (int j = 0; j < 4; ++j) ra[j] = ip[c + 64 * j];
    #pragma unroll
    for (int j = 0; j < 4; ++j) rb[j] = tp[c + 64 * j];

    float si = 0.f, st = 0.f, sd = 0.f;
    #pragma unroll
    for (int j = 0; j < 4; ++j) {
        int idx = c + 64 * j;
        ib[idx] = pack4_e4m3(ra[j]);
        tb[idx] = pack4_e4m3(rb[j]);
        si += ra[j].x*ra[j].x + ra[j].y*ra[j].y + ra[j].z*ra[j].z + ra[j].w*ra[j].w;
        st += rb[j].x*rb[j].x + rb[j].y*rb[j].y + rb[j].z*rb[j].z + rb[j].w*rb[j].w;
        sd += ra[j].x*rb[j].x + ra[j].y*rb[j].y + ra[j].z*rb[j].z + ra[j].w*rb[j].w;
    }

    __shared__ float sh[3][8];
    const int lane = t & 31, w = t >> 5;
    si = warp_sum(si); st = warp_sum(st); sd = warp_sum(sd);
    if (lane == 0) { sh[0][w] = si; sh[1][w] = st; sh[2][w] = sd; }
    __syncthreads();
    if (t < 4) {
        float fsi = sh[0][2*t] + sh[0][2*t + 1];
        float fst = sh[1][2*t] + sh[1][2*t + 1];
        float fsd = sh[2][2*t] + sh[2][2*t + 1];
        int grow = blockIdx.x * 4 + t;
        float ni = fmaxf(sqrtf(fsi), EPSN);
        float nt = fmaxf(sqrtf(fst), EPSN);
        g_rnorm_img[grow] = 1.0f / ni;
        g_rnorm_txt[grow] = 1.0f / nt;
        float e = 1.0f - fsd / (ni * nt);
        g_pos_part[grow] = e * e;
    }
}

#define CP_ASYNC16(dst, src) \
    asm volatile("cp.async.cg.shared.global [%0], [%1], 16;" :: "r"(dst), "l"(src) : "memory")
#define CP_COMMIT()  asm volatile("cp.async.commit_group;" ::: "memory")
#define CP_WAIT2()   asm volatile("cp.async.wait_group 2;" ::: "memory")

#define LDSM_X4(r0, r1, r2, r3, addr) \
    asm volatile("ldmatrix.sync.aligned.m8n8.x4.shared.b16 {%0,%1,%2,%3}, [%4];" \
        : "=r"(r0), "=r"(r1), "=r"(r2), "=r"(r3) : "r"(addr))

#define MMA_FP8(c, a, b) \
    asm volatile("mma.sync.aligned.m16n8k32.row.col.f32.e4m3.e4m3.f32 " \
        "{%0,%1,%2,%3}, {%4,%5,%6,%7}, {%8,%9}, {%0,%1,%2,%3};" \
        : "+f"((c)[0]), "+f"((c)[1]), "+f"((c)[2]), "+f"((c)[3]) \
        : "r"((a)[0]), "r"((a)[1]), "r"((a)[2]), "r"((a)[3]), "r"((b)[0]), "r"((b)[1]))

__global__ void __launch_bounds__(256, 3) gemm_neg_kernel()
{
    extern __shared__ char smem[];
    const uint32_t sbase = smem_u32(smem);
    const int tid  = threadIdx.x;
    const int lane = tid & 31;
    const int wid  = tid >> 5;
    const int wm   = (wid >> 2) * 64;   // warp m offset (0 or 64)
    const int wn   = (wid & 3) * 16;    // warp n offset (0,16,32,48)

    const int bi = blockIdx.y * BM;
    const int bj = blockIdx.x * BN;

    // Prefetch mapping.
    // A: 128 rows x 4 chunks(16B) = 512 -> 2 per thread (same as R8).
    // B: 64 rows x 4 chunks = 256 -> 1 per thread.
    const int pra  = tid >> 1;
    const int pca0 = (tid & 1) * 2;
    const uint8_t* aptr = g_img_f8 + (size_t)(bi + pra) * DIM + pca0 * 16;
    const uint32_t pda  = pra * SROW + pca0 * 16;
    const int prb  = tid >> 2;
    const int pcb  = tid & 3;
    const uint8_t* bptr = g_txt_f8 + (size_t)(bj + prb) * DIM + pcb * 16;
    const uint32_t pdb  = STAGE_A + prb * SROW + pcb * 16;

    float acc[4][2][4];
    #pragma unroll
    for (int i = 0; i < 4; ++i)
        #pragma unroll
        for (int j = 0; j < 2; ++j)
            #pragma unroll
            for (int k = 0; k < 4; ++k) acc[i][j][k] = 0.f;

    // Prologue: fill stages 0..2 (chunks 0..2)
    #pragma unroll
    for (int s = 0; s < STAGES - 1; ++s) {
        uint32_t sg = sbase + s * STAGE_BYTES;
        const uint8_t* as = aptr + s * BK;
        const uint8_t* bs = bptr + s * BK;
        CP_ASYNC16(sg + pda,      as);
        CP_ASYNC16(sg + pda + 16, as + 16);
        CP_ASYNC16(sg + pdb,      bs);
        CP_COMMIT();
    }

    // Hoisted ldmatrix offsets (relative to stage base)
    const int lrow  = (lane & 7) + ((lane >> 3) & 1) * 8;
    const int lboff = (lane >> 4) * 16;
    uint32_t aoffm[4], boffn;
    #pragma unroll
    for (int mf = 0; mf < 4; ++mf) aoffm[mf] = (wm + mf * 16 + lrow) * SROW + lboff;
    boffn = STAGE_A + (wn + lrow) * SROW + lboff;

    for (int kt = 0; kt < KT; ++kt) {
        const uint32_t sS = sbase + (kt & 3) * STAGE_BYTES;
        CP_WAIT2();
        __syncthreads();

        // Interleaved fragment loads + MMAs (R8 body, slimmer warp tile)
        #pragma unroll
        for (int ks = 0; ks < 2; ++ks) {
            uint32_t af[4][4], bf[2][2];
            #pragma unroll
            for (int mf = 0; mf < 4; ++mf)
                LDSM_X4(af[mf][0], af[mf][1], af[mf][2], af[mf][3],
                        sS + aoffm[mf] + ks * 32);
            {
                uint32_t r0, r1, r2, r3;
                LDSM_X4(r0, r1, r2, r3, sS + boffn + ks * 32);
                bf[0][0] = r0;  bf[1][0] = r1;
                bf[0][1] = r2;  bf[1][1] = r3;
            }
            #pragma unroll
            for (int mf = 0; mf < 4; ++mf)
                #pragma unroll
                for (int nf = 0; nf < 2; ++nf)
                    MMA_FP8(acc[mf][nf], af[mf], bf[nf]);
        }

        // Prefetch chunk kt+3 into stage (kt+3)&3 — consumed at iter kt-1;
        // the barrier above guarantees no warp still reads it.
        if (kt + STAGES - 1 < KT) {
            uint32_t sg = sbase + ((kt + STAGES - 1) & 3) * STAGE_BYTES;
            const uint8_t* as = aptr + (kt + STAGES - 1) * BK;
            const uint8_t* bs = bptr + (kt + STAGES - 1) * BK;
            CP_ASYNC16(sg + pda,      as);
            CP_ASYNC16(sg + pda + 16, as + 16);
            CP_ASYNC16(sg + pdb,      bs);
        }
        CP_COMMIT();   // uniform commit keeps wait_group counting exact
    }

    // ---- fused loss epilogue with sound max-screen ----
    const int groupRow = lane >> 2;
    const int col0 = (lane & 3) * 2;

    float ri0[4], ri1[4], rj[2][2];
    #pragma unroll
    for (int mf = 0; mf < 4; ++mf) {
        int gi0 = bi + wm + mf * 16 + groupRow;
        ri0[mf] = __ldg(&g_rnorm_img[gi0]);
        ri1[mf] = __ldg(&g_rnorm_img[gi0 + 8]);
    }
    #pragma unroll
    for (int nf = 0; nf < 2; ++nf) {
        int gj = bj + wn + nf * 8 + col0;
        rj[nf][0] = __ldg(&g_rnorm_txt[gj]);
        rj[nf][1] = __ldg(&g_rnorm_txt[gj + 1]);
    }

    // Screen: max over raw accumulators (only positive sims can pass the margin)
    float amax = 0.f;
    #pragma unroll
    for (int mf = 0; mf < 4; ++mf)
        #pragma unroll
        for (int nf = 0; nf < 2; ++nf) {
            float m01 = fmaxf(acc[mf][nf][0], acc[mf][nf][1]);
            float m23 = fmaxf(acc[mf][nf][2], acc[mf][nf][3]);
            amax = fmaxf(amax, fmaxf(m01, m23));
        }
    float rim = 0.f, rjm = 0.f;
    #pragma unroll
    for (int mf = 0; mf < 4; ++mf) rim = fmaxf(rim, fmaxf(ri0[mf], ri1[mf]));
    #pragma unroll
    for (int nf = 0; nf < 2; ++nf) rjm = fmaxf(rjm, fmaxf(rj[nf][0], rj[nf][1]));

    float local = 0.f;
    // Upper bound on any sim in this thread's sub-tile: amax*rim*rjm (rnorms > 0).
    if (amax * rim * rjm > MARGIN) {
        #pragma unroll
        for (int mf = 0; mf < 4; ++mf) {
            int gi0 = bi + wm + mf * 16 + groupRow;
            int gi1 = gi0 + 8;
            #pragma unroll
            for (int nf = 0; nf < 2; ++nf) {
                int gj0 = bj + wn + nf * 8 + col0;
                int gj1 = gj0 + 1;
                float s0 = acc[mf][nf][0] * ri0[mf] * rj[nf][0];
                float s1 = acc[mf][nf][1] * ri0[mf] * rj[nf][1];
                float s2 = acc[mf][nf][2] * ri1[mf] * rj[nf][0];
                float s3 = acc[mf][nf][3] * ri1[mf] * rj[nf][1];
                float d0 = s0 - MARGIN, d1 = s1 - MARGIN;
                float d2 = s2 - MARGIN, d3 = s3 - MARGIN;
                if (gi0 != gj0 && d0 > 0.f) local += d0 * d0;
                if (gi0 != gj1 && d1 > 0.f) local += d1 * d1;
                if (gi1 != gj0 && d2 > 0.f) local += d2 * d2;
                if (gi1 != gj1 && d3 > 0.f) local += d3 * d3;
            }
        }
    }

    __shared__ float red[8];
    local = warp_sum(local);
    if (lane == 0) red[wid] = local;
    __syncthreads();
    if (wid == 0) {
        local = (lane < 8) ? red[lane] : 0.f;
        #pragma unroll
        for (int o = 4; o > 0; o >>= 1)
            local += __shfl_down_sync(0xffffffffu, local, o);
        if (lane == 0) g_neg_part[blockIdx.y * NBLK_J + blockIdx.x] = local;
    }
}

__global__ void __launch_bounds__(256) finalize_kernel(float* __restrict__ out) {
    const int tid = threadIdx.x;
    float sp = 0.f, sn = 0.f;
    #pragma unroll 4
    for (int i = tid; i < NROWS; i += 256) sp += g_pos_part[i];
    for (int i = tid; i < NBLKS; i += 256) sn += g_neg_part[i];

    __shared__ float shp[8], shn[8];
    int lane = tid & 31, wid = tid >> 5;
    sp = warp_sum(sp); sn = warp_sum(sn);
    if (lane == 0) { shp[wid] = sp; shn[wid] = sn; }
    __syncthreads();
    if (wid == 0) {
        sp = (lane < 8) ? shp[lane] : 0.f;
        sn = (lane < 8) ? shn[lane] : 0.f;
        #pragma unroll
        for (int o = 4; o > 0; o >>= 1) {
            sp += __shfl_down_sync(0xffffffffu, sp, o);
            sn += __shfl_down_sync(0xffffffffu, sn, o);
        }
        if (lane == 0) {
            const float n = (float)NROWS;
            out[0] = sp / n + sn / (n * n);
        }
    }
}

extern "C" void kernel_launch(void* const* d_in, const int* in_sizes, int n_in,
                              void* d_out, int out_size) {
    const float* img = (const float*)d_in[0];
    const float* txt = (const float*)d_in[1];
    float* out = (float*)d_out;

    cudaFuncSetAttribute(gemm_neg_kernel, cudaFuncAttributeMaxDynamicSharedMemorySize, SMEM_BYTES);

    row_stats_convert_kernel<<<NROWS / 4, 256>>>(img, txt);
    dim3 grid(NBLK_J, NBLK_I);   // (64, 32)
    gemm_neg_kernel<<<grid, 256, SMEM_BYTES>>>();
    finalize_kernel<<<1, 256>>>(out);
}

// round 15
// speedup vs baseline: 1.1301x; 1.1301x over previous
#include <cuda_runtime.h>
#include <cuda_fp8.h>
#include <cstdint>
#include <math.h>

#define NROWS 4096
#define DIM   1024
#define MARGIN 0.5f
#define EPSN   1e-8f

#define BM 128
#define BN 128
#define BK 64                 // 64 fp8 bytes per k-chunk
#define KT (DIM / BK)         // 16
#define STAGES 4
#define SROW 80               // padded smem row stride (bytes) for 64B of data
#define STAGE_A (BM * SROW)
#define STAGE_B (BN * SROW)
#define STAGE_BYTES (STAGE_A + STAGE_B)        // 20480
#define SMEM_BYTES (STAGES * STAGE_BYTES)      // 81920

#define NBLK_I (NROWS / BM)   // 32
#define NBLK_J (NROWS / BN)   // 32
#define NBLKS  (NBLK_I * NBLK_J)

// Scratch (device globals; rewritten every call)
__device__ uint8_t g_img_f8[NROWS * DIM];
__device__ uint8_t g_txt_f8[NROWS * DIM];
__device__ float g_rnorm_img[NROWS];
__device__ float g_rnorm_txt[NROWS];
__device__ float g_pos_part[NROWS];
__device__ float g_neg_part[NBLKS];

__device__ __forceinline__ uint32_t smem_u32(const void* p) {
    uint32_t a;
    asm("{ .reg .u64 t; cvta.to.shared.u64 t, %1; cvt.u32.u64 %0, t; }" : "=r"(a) : "l"(p));
    return a;
}

__device__ __forceinline__ float warp_sum(float v) {
    #pragma unroll
    for (int o = 16; o > 0; o >>= 1) v += __shfl_down_sync(0xffffffffu, v, o);
    return v;
}

__device__ __forceinline__ uint32_t pack4_e4m3(float4 v) {
    __nv_fp8x2_storage_t lo = __nv_cvt_float2_to_fp8x2(make_float2(v.x, v.y),
                                                       __NV_SATFINITE, __NV_E4M3);
    __nv_fp8x2_storage_t hi = __nv_cvt_float2_to_fp8x2(make_float2(v.z, v.w),
                                                       __NV_SATFINITE, __NV_E4M3);
    return (uint32_t)lo | ((uint32_t)hi << 16);
}

// Fused: fp32 read -> fp8 copies + norms + positive-loss partial. 4 rows per block.
// R11 layout: per-instruction coalesced loads (stride 64 float4 across j), MLP=8.
__global__ void __launch_bounds__(256) row_stats_convert_kernel(
    const float* __restrict__ img, const float* __restrict__ txt)
{
    const int t   = threadIdx.x;
    const int rl  = t >> 6;
    const int c   = t & 63;
    const int row = blockIdx.x * 4 + rl;

    const float4* ip = reinterpret_cast<const float4*>(img + (size_t)row * DIM);
    const float4* tp = reinterpret_cast<const float4*>(txt + (size_t)row * DIM);
    uint32_t* ib = reinterpret_cast<uint32_t*>(g_img_f8 + (size_t)row * DIM);
    uint32_t* tb = reinterpret_cast<uint32_t*>(g_txt_f8 + (size_t)row * DIM);

    float4 ra[4], rb[4];
    #pragma unroll
    for (int j = 0; j < 4; ++j) ra[j] = ip[c + 64 * j];
    #pragma unroll
    for (int j = 0; j < 4; ++j) rb[j] = tp[c + 64 * j];

    float si = 0.f, st = 0.f, sd = 0.f;
    #pragma unroll
    for (int j = 0; j < 4; ++j) {
        int idx = c + 64 * j;
        ib[idx] = pack4_e4m3(ra[j]);
        tb[idx] = pack4_e4m3(rb[j]);
        si += ra[j].x*ra[j].x + ra[j].y*ra[j].y + ra[j].z*ra[j].z + ra[j].w*ra[j].w;
        st += rb[j].x*rb[j].x + rb[j].y*rb[j].y + rb[j].z*rb[j].z + rb[j].w*rb[j].w;
        sd += ra[j].x*rb[j].x + ra[j].y*rb[j].y + ra[j].z*rb[j].z + ra[j].w*rb[j].w;
    }

    __shared__ float sh[3][8];
    const int lane = t & 31, w = t >> 5;
    si = warp_sum(si); st = warp_sum(st); sd = warp_sum(sd);
    if (lane == 0) { sh[0][w] = si; sh[1][w] = st; sh[2][w] = sd; }
    __syncthreads();
    if (t < 4) {
        float fsi = sh[0][2*t] + sh[0][2*t + 1];
        float fst = sh[1][2*t] + sh[1][2*t + 1];
        float fsd = sh[2][2*t] + sh[2][2*t + 1];
        int grow = blockIdx.x * 4 + t;
        float ni = fmaxf(sqrtf(fsi), EPSN);
        float nt = fmaxf(sqrtf(fst), EPSN);
        g_rnorm_img[grow] = 1.0f / ni;
        g_rnorm_txt[grow] = 1.0f / nt;
        float e = 1.0f - fsd / (ni * nt);
        g_pos_part[grow] = e * e;
    }
}

#define CP_ASYNC16(dst, src) \
    asm volatile("cp.async.cg.shared.global [%0], [%1], 16;" :: "r"(dst), "l"(src) : "memory")
#define CP_COMMIT()  asm volatile("cp.async.commit_group;" ::: "memory")
#define CP_WAIT2()   asm volatile("cp.async.wait_group 2;" ::: "memory")

#define LDSM_X4(r0, r1, r2, r3, addr) \
    asm volatile("ldmatrix.sync.aligned.m8n8.x4.shared.b16 {%0,%1,%2,%3}, [%4];" \
        : "=r"(r0), "=r"(r1), "=r"(r2), "=r"(r3) : "r"(addr))

#define MMA_FP8(c, a, b) \
    asm volatile("mma.sync.aligned.m16n8k32.row.col.f32.e4m3.e4m3.f32 " \
        "{%0,%1,%2,%3}, {%4,%5,%6,%7}, {%8,%9}, {%0,%1,%2,%3};" \
        : "+f"((c)[0]), "+f"((c)[1]), "+f"((c)[2]), "+f"((c)[3]) \
        : "r"((a)[0]), "r"((a)[1]), "r"((a)[2]), "r"((a)[3]), "r"((b)[0]), "r"((b)[1]))

__global__ void __launch_bounds__(256, 2) gemm_neg_kernel()
{
    extern __shared__ char smem[];
    const uint32_t sbase = smem_u32(smem);
    const int tid  = threadIdx.x;
    const int lane = tid & 31;
    const int wid  = tid >> 5;
    const int wm   = (wid >> 2) * 64;   // warp m offset (0 or 64)
    const int wn   = (wid & 3) * 32;    // warp n offset (0,32,64,96)

    const int bi = blockIdx.y * BM;
    const int bj = blockIdx.x * BN;

    // Prefetch source pointers (hoisted)
    const int pr  = tid >> 1;
    const int pc0 = (tid & 1) * 2;
    const uint8_t* aptr = g_img_f8 + (size_t)(bi + pr) * DIM + pc0 * 16;
    const uint8_t* bptr = g_txt_f8 + (size_t)(bj + pr) * DIM + pc0 * 16;
    const uint32_t pda = pr * SROW + pc0 * 16;

    float acc[4][4][4];
    #pragma unroll
    for (int i = 0; i < 4; ++i)
        #pragma unroll
        for (int j = 0; j < 4; ++j)
            #pragma unroll
            for (int k = 0; k < 4; ++k) acc[i][j][k] = 0.f;

    // Prologue: fill stages 0..2 (chunks 0..2)
    #pragma unroll
    for (int s = 0; s < STAGES - 1; ++s) {
        uint32_t sa = sbase + s * STAGE_BYTES;
        uint32_t sb = sa + STAGE_A;
        const uint8_t* as = aptr + s * BK;
        const uint8_t* bs = bptr + s * BK;
        CP_ASYNC16(sa + pda,      as);
        CP_ASYNC16(sa + pda + 16, as + 16);
        CP_ASYNC16(sb + pda,      bs);
        CP_ASYNC16(sb + pda + 16, bs + 16);
        CP_COMMIT();
    }

    // Hoisted ldmatrix offsets (relative to stage base)
    const int lrow  = (lane & 7) + ((lane >> 3) & 1) * 8;
    const int lboff = (lane >> 4) * 16;
    uint32_t aoffm[4], boffn[2];
    #pragma unroll
    for (int mf = 0; mf < 4; ++mf) aoffm[mf] = (wm + mf * 16 + lrow) * SROW + lboff;
    #pragma unroll
    for (int nf2 = 0; nf2 < 2; ++nf2) boffn[nf2] = STAGE_A + (wn + nf2 * 16 + lrow) * SROW + lboff;

    // FULL UNROLL: stage indices (kt&3) become compile-time constants so all
    // LDSM / cp.async addresses fold into immediate offsets (kills IMAD/IADD3
    // issue traffic — the alu+fma 37% seen in ncu).
    #pragma unroll
    for (int kt = 0; kt < KT; ++kt) {
        const uint32_t sS = sbase + (kt & 3) * STAGE_BYTES;
        CP_WAIT2();
        __syncthreads();

        // Interleaved fragment loads + MMAs (the proven R4/R8 inner body)
        #pragma unroll
        for (int ks = 0; ks < 2; ++ks) {
            uint32_t af[4][4], bf[4][2];
            #pragma unroll
            for (int mf = 0; mf < 4; ++mf)
                LDSM_X4(af[mf][0], af[mf][1], af[mf][2], af[mf][3],
                        sS + aoffm[mf] + ks * 32);
            #pragma unroll
            for (int nf2 = 0; nf2 < 2; ++nf2) {
                uint32_t r0, r1, r2, r3;
                LDSM_X4(r0, r1, r2, r3, sS + boffn[nf2] + ks * 32);
                bf[nf2 * 2][0] = r0;     bf[nf2 * 2 + 1][0] = r1;
                bf[nf2 * 2][1] = r2;     bf[nf2 * 2 + 1][1] = r3;
            }
            #pragma unroll
            for (int mf = 0; mf < 4; ++mf)
                #pragma unroll
                for (int nf = 0; nf < 4; ++nf)
                    MMA_FP8(acc[mf][nf], af[mf], bf[nf]);
        }

        // Prefetch chunk kt+3 into stage (kt+3)&3 — consumed at iter kt-1;
        // the barrier above already guarantees no warp still reads it.
        if (kt + STAGES - 1 < KT) {
            uint32_t sa = sbase + ((kt + STAGES - 1) & 3) * STAGE_BYTES;
            uint32_t sb = sa + STAGE_A;
            const uint8_t* as = aptr + (kt + STAGES - 1) * BK;
            const uint8_t* bs = bptr + (kt + STAGES - 1) * BK;
            CP_ASYNC16(sa + pda,      as);
            CP_ASYNC16(sa + pda + 16, as + 16);
            CP_ASYNC16(sb + pda,      bs);
            CP_ASYNC16(sb + pda + 16, bs + 16);
        }
        CP_COMMIT();   // uniform commit keeps wait_group counting exact
    }

    // ---- fused loss epilogue with sound max-screen ----
    const int groupRow = lane >> 2;
    const int col0 = (lane & 3) * 2;

    float ri0[4], ri1[4], rj[4][2];
    #pragma unroll
    for (int mf = 0; mf < 4; ++mf) {
        int gi0 = bi + wm + mf * 16 + groupRow;
        ri0[mf] = __ldg(&g_rnorm_img[gi0]);
        ri1[mf] = __ldg(&g_rnorm_img[gi0 + 8]);
    }
    #pragma unroll
    for (int nf = 0; nf < 4; ++nf) {
        int gj = bj + wn + nf * 8 + col0;
        rj[nf][0] = __ldg(&g_rnorm_txt[gj]);
        rj[nf][1] = __ldg(&g_rnorm_txt[gj + 1]);
    }

    // Screen: max over raw accumulators (only positive sims can pass the margin)
    float amax = 0.f;
    #pragma unroll
    for (int mf = 0; mf < 4; ++mf)
        #pragma unroll
        for (int nf = 0; nf < 4; ++nf) {
            float m01 = fmaxf(acc[mf][nf][0], acc[mf][nf][1]);
            float m23 = fmaxf(acc[mf][nf][2], acc[mf][nf][3]);
            amax = fmaxf(amax, fmaxf(m01, m23));
        }
    float rim = 0.f, rjm = 0.f;
    #pragma unroll
    for (int mf = 0; mf < 4; ++mf) rim = fmaxf(rim, fmaxf(ri0[mf], ri1[mf]));
    #pragma unroll
    for (int nf = 0; nf < 4; ++nf) rjm = fmaxf(rjm, fmaxf(rj[nf][0], rj[nf][1]));

    float local = 0.f;
    // Upper bound on any sim in this thread's sub-tile: amax*rim*rjm (rnorms > 0).
    if (amax * rim * rjm > MARGIN) {
        #pragma unroll
        for (int mf = 0; mf < 4; ++mf) {
            int gi0 = bi + wm + mf * 16 + groupRow;
            int gi1 = gi0 + 8;
            #pragma unroll
            for (int nf = 0; nf < 4; ++nf) {
                int gj0 = bj + wn + nf * 8 + col0;
                int gj1 = gj0 + 1;
                float s0 = acc[mf][nf][0] * ri0[mf] * rj[nf][0];
                float s1 = acc[mf][nf][1] * ri0[mf] * rj[nf][1];
                float s2 = acc[mf][nf][2] * ri1[mf] * rj[nf][0];
                float s3 = acc[mf][nf][3] * ri1[mf] * rj[nf][1];
                float d0 = s0 - MARGIN, d1 = s1 - MARGIN;
                float d2 = s2 - MARGIN, d3 = s3 - MARGIN;
                if (gi0 != gj0 && d0 > 0.f) local += d0 * d0;
                if (gi0 != gj1 && d1 > 0.f) local += d1 * d1;
                if (gi1 != gj0 && d2 > 0.f) local += d2 * d2;
                if (gi1 != gj1 && d3 > 0.f) local += d3 * d3;
            }
        }
    }

    __shared__ float red[8];
    local = warp_sum(local);
    if (lane == 0) red[wid] = local;
    __syncthreads();
    if (wid == 0) {
        local = (lane < 8) ? red[lane] : 0.f;
        #pragma unroll
        for (int o = 4; o > 0; o >>= 1)
            local += __shfl_down_sync(0xffffffffu, local, o);
        if (lane == 0) g_neg_part[blockIdx.y * NBLK_J + blockIdx.x] = local;
    }
}

__global__ void __launch_bounds__(256) finalize_kernel(float* __restrict__ out) {
    const int tid = threadIdx.x;
    float sp = 0.f, sn = 0.f;
    #pragma unroll 4
    for (int i = tid; i < NROWS; i += 256) sp += g_pos_part[i];
    for (int i = tid; i < NBLKS; i += 256) sn += g_neg_part[i];

    __shared__ float shp[8], shn[8];
    int lane = tid & 31, wid = tid >> 5;
    sp = warp_sum(sp); sn = warp_sum(sn);
    if (lane == 0) { shp[wid] = sp; shn[wid] = sn; }
    __syncthreads();
    if (wid == 0) {
        sp = (lane < 8) ? shp[lane] : 0.f;
        sn = (lane < 8) ? shn[lane] : 0.f;
        #pragma unroll
        for (int o = 4; o > 0; o >>= 1) {
            sp += __shfl_down_sync(0xffffffffu, sp, o);
            sn += __shfl_down_sync(0xffffffffu, sn, o);
        }
        if (lane == 0) {
            const float n = (float)NROWS;
            out[0] = sp / n + sn / (n * n);
        }
    }
}

extern "C" void kernel_launch(void* const* d_in, const int* in_sizes, int n_in,
                              void* d_out, int out_size) {
    const float* img = (const float*)d_in[0];
    const float* txt = (const float*)d_in[1];
    float* out = (float*)d_out;

    cudaFuncSetAttribute(gemm_neg_kernel, cudaFuncAttributeMaxDynamicSharedMemorySize, SMEM_BYTES);

    row_stats_convert_kernel<<<NROWS / 4, 256>>>(img, txt);
    dim3 grid(NBLK_J, NBLK_I);   // (32, 32)
    gemm_neg_kernel<<<grid, 256, SMEM_BYTES>>>();
    finalize_kernel<<<1, 256>>>(out);
}